// round 14
// baseline (speedup 1.0000x reference)
#include <cuda_runtime.h>

#define BB 16
#define CIN 256
#define FF 76
#define NPIX (FF*FF)          /* 5776 */
#define NA 3
#define NCH 85
#define KK 50
#define PXB 160               /* pixels per block */
#define TPB 320               /* 10 warps: 4 quarters x 80 pairs */
#define NPAIR 80
#define NBLK 37
#define TOTB (NBLK*BB)        /* 592 = 148*4 exactly */
#define ST (NPIX/2)           /* 2888 ulls per channel */

typedef unsigned long long ull;

__device__ double       g_acc[5];
__device__ unsigned int g_done;

__constant__ float c_AW[9] = {1.25f,2.0f,4.125f,3.75f,7.75f,7.375f,14.5f,19.5f,46.625f};
__constant__ float c_AH[9] = {1.625f,3.75f,2.875f,7.625f,5.625f,14.875f,11.25f,24.75f,40.75f};
__constant__ float c_MW[3] = {1.25f,2.0f,4.125f};
__constant__ float c_MH[3] = {1.625f,3.75f,2.875f};

/* union: w2 (conv phase) -> part (combine phase) */
union UShared {
    ull w2[15][CIN];            /* 30720 B */
    ull part[4][15][NPAIR];     /* 38400 B */
};
struct SMem {
    UShared u;
    float  out5[NA][PXB][5];    /* 9600 B, separate (written in epilogue) */
    float  sB[15];
    float  sTx[KK], sTy[KK], sTw[KK], sTh[KK];
    float  sX1[KK], sY1[KK], sX2[KK], sY2[KK], sAr[KK];
    int    sCls[KK];
    int    sOwn[NA*PXB];
    int    sPos[KK];
    int    sCnt;
    float  sX[CIN];
    double red[5][10];
};

__device__ __forceinline__ float sigf(float x){ return 1.0f/(1.0f + expf(-x)); }

__device__ __forceinline__ float bce1(float p, float t){
    float pc = fminf(fmaxf(p, 1e-12f), 0.99999988f);
    return -(t*logf(pc) + (1.0f - t)*logf(1.0f - pc));
}

__device__ __forceinline__ void fma2(ull& acc, ull a, ull b){
    asm("fma.rn.f32x2 %0, %1, %2, %0;" : "+l"(acc) : "l"(a), "l"(b));
}
__device__ __forceinline__ ull add2(ull a, ull b){
    ull r; asm("add.rn.f32x2 %0, %1, %2;" : "=l"(r) : "l"(a), "l"(b)); return r;
}
__device__ __forceinline__ float2 u2f2(ull v){
    float2 r; asm("mov.b64 {%0, %1}, %2;" : "=f"(r.x), "=f"(r.y) : "l"(v)); return r;
}

__global__ void __launch_bounds__(TPB, 4)
k_main(const float* __restrict__ xin, const float* __restrict__ labels,
       const float* __restrict__ cw,  const float* __restrict__ cb,
       float* __restrict__ dout)
{
    extern __shared__ __align__(16) char smraw[];
    SMem* sm = reinterpret_cast<SMem*>(smraw);

    int tid = threadIdx.x;
    int b   = blockIdx.y;
    int n0  = blockIdx.x*PXB;
    int npb = NPIX - n0; if (npb > PXB) npb = PXB;   /* 160 or 16 */

    for (int i = tid; i < NA*PXB; i += TPB) sm->sOwn[i] = -1;
    if (tid == 0) sm->sCnt = 0;

    /* weights as (w,w) pairs (phase: w2) */
    for (int i = tid; i < 15*CIN; i += TPB){
        int j = i >> 8, c = i & 255;
        int a = j/5, ch = j%5;
        float w = cw[(a*NCH + ch)*CIN + c];
        float2 p = make_float2(w, w);
        sm->u.w2[j][c] = *reinterpret_cast<ull*>(&p);
    }
    if (tid < 15){ int a = tid/5, ch = tid%5; sm->sB[tid] = cb[a*NCH + ch]; }
    if (tid >= 64 && tid < 64 + KK){
        int t = tid - 64;
        const float* L = labels + (b*KK + t)*5;
        float cls=L[0], xc=L[1], yc=L[2], w=L[3], h=L[4];
        bool valid = (cls + xc + yc + w + h) > 0.0f;
        float tx = xc*(float)FF, ty = yc*(float)FF;
        float tw = w *(float)FF, th = h *(float)FF;
        sm->sTx[t]=tx; sm->sTy[t]=ty; sm->sTw[t]=tw; sm->sTh[t]=th;
        sm->sCls[t] = (int)cls;
        if (valid){
            sm->sX1[t]=tx-tw*0.5f; sm->sY1[t]=ty-th*0.5f;
            sm->sX2[t]=tx+tw*0.5f; sm->sY2[t]=ty+th*0.5f;
            sm->sAr[t]=tw*th;
        } else {
            sm->sX1[t]= 3.0e38f; sm->sY1[t]= 3.0e38f;
            sm->sX2[t]=-3.0e38f; sm->sY2[t]=-3.0e38f;
            sm->sAr[t]= 0.0f;
        }
        float ta = tw*th;
        float best = -1.0f; int bn = 0;
        #pragma unroll
        for (int a = 0; a < 9; a++){
            float inter = fminf(tw, c_AW[a]) * fminf(th, c_AH[a]);
            float iou = inter / (ta + c_AW[a]*c_AH[a] - inter);
            if (iou > best){ best = iou; bn = a; }
        }
        if (valid && bn < 3){
            int ii = (int)tx, jj = (int)ty;
            int slot = jj*FF + ii - n0;
            if (slot >= 0 && slot < PXB) atomicMax(&sm->sOwn[bn*PXB + slot], t);
        }
    }
    __syncthreads();

    int q    = tid / NPAIR;      /* channel quarter 0..3 (warp-quasi-uniform) */
    int pair = tid - q*NPAIR;    /* pixel pair 0..79 */
    bool pvc = (2*pair < npb);
    int pb = pvc ? pair : 0;

    /* ---- conv: 2 pixels x 64 channels per thread, f32x2, prefetch-2 ---- */
    ull acc[15];
    #pragma unroll
    for (int j = 0; j < 15; j++) acc[j] = 0ULL;
    {
        const ull* xp = reinterpret_cast<const ull*>(xin + (size_t)b*CIN*NPIX)
                        + (size_t)(q*64)*ST + (n0 >> 1) + pb;
        const ull* wrow = &sm->u.w2[0][q*64];
        ull x0 = xp[0], x1 = xp[ST];
        #pragma unroll 1
        for (int c = 0; c < 62; c += 2){
            const ull* xn = xp + 2*ST;
            ull y0 = xn[0], y1 = xn[ST];
            #pragma unroll
            for (int j = 0; j < 15; j++){
                ulonglong2 wA = *reinterpret_cast<const ulonglong2*>(wrow + (size_t)j*CIN + c);
                fma2(acc[j], wA.x, x0);
                fma2(acc[j], wA.y, x1);
            }
            x0 = y0; x1 = y1; xp = xn;
        }
        #pragma unroll
        for (int j = 0; j < 15; j++){
            ulonglong2 wA = *reinterpret_cast<const ulonglong2*>(wrow + (size_t)j*CIN + 62);
            fma2(acc[j], wA.x, x0);
            fma2(acc[j], wA.y, x1);
        }
    }
    __syncthreads();   /* all w2 reads done -> union becomes part */
    #pragma unroll
    for (int j = 0; j < 15; j++) sm->u.part[q][j][pair] = acc[j];
    __syncthreads();

    double l_xy=0.0, l_wh=0.0, l_obj=0.0, l_cl=0.0, l_l2=0.0;

    /* ---- each thread tid<npb finalizes ONE pixel, per-anchor to cap regs ---- */
    if (tid < npb){
        int slot = tid;
        int n = n0 + slot;
        int pr = slot >> 1;
        int hf = slot & 1;
        int h = n / FF, w = n % FF;

        #pragma unroll
        for (int a = 0; a < NA; a++){
            float a5[5];
            #pragma unroll
            for (int t = 0; t < 5; t++){
                int j = a*5 + t;
                ull s01 = add2(sm->u.part[0][j][pr], sm->u.part[1][j][pr]);
                ull s23 = add2(sm->u.part[2][j][pr], sm->u.part[3][j][pr]);
                float2 f = u2f2(add2(s01, s23));
                a5[t] = (hf ? f.y : f.x) + sm->sB[j];
            }
            float s0 = sigf(a5[0]), s1 = sigf(a5[1]), s4 = sigf(a5[4]);
            float px = s0 + (float)w, py = s1 + (float)h;
            float pw = expf(a5[2])*c_MW[a], ph = expf(a5[3])*c_MH[a];
            float bx1 = px - pw*0.5f, by1 = py - ph*0.5f;
            float bx2 = px + pw*0.5f, by2 = py + ph*0.5f;
            float bap = pw*ph;

            bool ign = false;
            #pragma unroll 2
            for (int k = 0; k < KK; k++){
                float dx = fminf(bx2, sm->sX2[k]) - fmaxf(bx1, sm->sX1[k]);
                float dy = fminf(by2, sm->sY2[k]) - fmaxf(by1, sm->sY1[k]);
                float inter = dx*dy;
                bool en = (dx > 0.0f) & (dy > 0.0f);
                ign = ign | (en & (inter > 0.7f*(bap + sm->sAr[k] - inter)));
            }

            int cell = (b*NA + a)*NPIX + n;
            int k = sm->sOwn[a*PXB + slot];
            bool m = (k >= 0);
            float obj = m ? 1.0f : (ign ? 0.0f : 1.0f);
            float o4 = s4 * obj;
            float* d5 = &sm->out5[a][slot][0];

            if (m){
                float tx = sm->sTx[k], ty = sm->sTy[k];
                float tw = sm->sTw[k], th = sm->sTh[k];
                int ii = (int)tx, jj = (int)ty;
                float tfx = tx - (float)ii, tfy = ty - (float)jj;
                float lw = logf(tw / c_MW[a] + 1e-16f);
                float lh = logf(th / c_MH[a] + 1e-16f);
                float sc  = sqrtf(2.0f - tw*th/(float)NPIX);
                float sc2 = sc*sc;
                l_xy += (double)((bce1(s0, tfx) + bce1(s1, tfy)) * sc2);
                float ow2 = a5[2]*sc, ow3 = a5[3]*sc;
                float tw2 = lw*sc, tw3 = lh*sc;
                float d2 = ow2 - tw2, d3 = ow3 - tw3;
                l_wh += 0.5*(double)(d2*d2 + d3*d3);
                l_obj += (double)bce1(o4, 1.0f);
                float e0 = s0 - tfx, e1 = s1 - tfy, e4 = o4 - 1.0f;
                l_l2 += (double)(e0*e0 + e1*e1 + d2*d2 + d3*d3 + e4*e4);
                int idx = atomicAdd(&sm->sCnt, 1);
                sm->sPos[idx] = (cell << 7) | sm->sCls[k];
                d5[0]=s0; d5[1]=s1; d5[2]=ow2; d5[3]=ow3; d5[4]=o4;
            } else {
                l_obj += (double)bce1(o4, 0.0f);
                l_l2  += (double)(o4*o4);
                d5[0]=0.0f; d5[1]=0.0f; d5[2]=0.0f; d5[3]=0.0f; d5[4]=o4;
            }
        }
    }
    __syncthreads();

    /* ---- single-pass coalesced store of the 3 output regions ---- */
    #pragma unroll
    for (int a = 0; a < NA; a++){
        size_t e0 = 6 + ((size_t)((b*NA + a)*NPIX + n0))*NCH;
        float* base = dout + e0;
        int cnt = npb*NCH;
        int pad = (int)((4 - (e0 & 3)) & 3);
        if (pad > cnt) pad = cnt;
        if (tid < pad){
            int cell = tid/NCH, c = tid - cell*NCH;
            base[tid] = (c < 5) ? sm->out5[a][cell][c] : 0.0f;
        }
        int nv = (cnt - pad) >> 2;
        float4* b4 = (float4*)(base + pad);
        for (int j = tid; j < nv; j += TPB){
            int g = pad + (j << 2);
            float4 vv;
            { int cell = g/NCH,     c = g     - cell*NCH; vv.x = (c < 5) ? sm->out5[a][cell][c] : 0.0f; }
            { int cell = (g+1)/NCH, c = (g+1) - cell*NCH; vv.y = (c < 5) ? sm->out5[a][cell][c] : 0.0f; }
            { int cell = (g+2)/NCH, c = (g+2) - cell*NCH; vv.z = (c < 5) ? sm->out5[a][cell][c] : 0.0f; }
            { int cell = (g+3)/NCH, c = (g+3) - cell*NCH; vv.w = (c < 5) ? sm->out5[a][cell][c] : 0.0f; }
            b4[j] = vv;
        }
        int rem0 = pad + (nv << 2);
        if (rem0 + tid < cnt){
            int g = rem0 + tid;
            int cell = g/NCH, c = g - cell*NCH;
            base[g] = (c < 5) ? sm->out5[a][cell][c] : 0.0f;
        }
    }
    __syncthreads();

    /* ---- class pass: 10 warps x 8 classes per positive ---- */
    {
        int lane = tid & 31, wid = tid >> 5;   /* wid 0..9 */
        int cnt = sm->sCnt;
        for (int qd = 0; qd < cnt; qd++){
            int pk   = sm->sPos[qd];
            int cell = pk >> 7;
            int cls  = pk & 127;
            int a    = (cell / NPIX) % NA;
            int pix  = cell % NPIX;
            for (int i = tid; i < CIN; i += TPB)
                sm->sX[i] = xin[((size_t)b*CIN + i)*NPIX + pix];
            __syncthreads();

            const float* wbase = cw + (size_t)(a*NCH + 5 + wid*8)*CIN;
            float s[8];
            #pragma unroll
            for (int i = 0; i < 8; i++) s[i] = 0.0f;
            #pragma unroll
            for (int j = 0; j < 8; j++){
                float x = sm->sX[lane + 32*j];
                #pragma unroll
                for (int i = 0; i < 8; i++)
                    s[i] += wbase[(size_t)i*CIN + lane + 32*j] * x;
            }
            #pragma unroll
            for (int i = 0; i < 8; i++){
                #pragma unroll
                for (int off = 16; off; off >>= 1)
                    s[i] += __shfl_down_sync(0xffffffffu, s[i], off);
            }
            if (lane == 0){
                float* oc = dout + 6 + (size_t)cell*NCH;
                #pragma unroll
                for (int i = 0; i < 8; i++){
                    int c = wid*8 + i;
                    float raw = s[i] + cb[a*NCH + 5 + c];
                    float sg = sigf(raw);
                    float t = (c == cls) ? 1.0f : 0.0f;
                    l_cl += (double)bce1(sg, t);
                    float d = sg - t;
                    l_l2 += (double)(d*d);
                    oc[5 + c] = sg;
                }
            }
            __syncthreads();
        }
    }

    /* ---- block reduce 5 doubles -> atomicAdd ---- */
    int lane = tid & 31, wid = tid >> 5;
    #pragma unroll
    for (int off = 16; off; off >>= 1){
        l_xy  += __shfl_down_sync(0xffffffffu, l_xy,  off);
        l_wh  += __shfl_down_sync(0xffffffffu, l_wh,  off);
        l_obj += __shfl_down_sync(0xffffffffu, l_obj, off);
        l_cl  += __shfl_down_sync(0xffffffffu, l_cl,  off);
        l_l2  += __shfl_down_sync(0xffffffffu, l_l2,  off);
    }
    if (lane == 0){
        sm->red[0][wid]=l_xy; sm->red[1][wid]=l_wh; sm->red[2][wid]=l_obj;
        sm->red[3][wid]=l_cl; sm->red[4][wid]=l_l2;
    }
    __syncthreads();
    if (tid == 0){
        double a0=0,a1=0,a2s=0,a3=0,a4=0;
        #pragma unroll
        for (int i = 0; i < 10; i++){
            a0+=sm->red[0][i]; a1+=sm->red[1][i]; a2s+=sm->red[2][i];
            a3+=sm->red[3][i]; a4+=sm->red[4][i];
        }
        atomicAdd(&g_acc[0], a0);
        atomicAdd(&g_acc[1], a1);
        atomicAdd(&g_acc[2], a2s);
        atomicAdd(&g_acc[3], a3);
        atomicAdd(&g_acc[4], a4);

        __threadfence();
        unsigned int t = atomicInc(&g_done, TOTB - 1);
        if (t == TOTB - 1){
            double xy = atomicAdd(&g_acc[0], 0.0);
            double wh = atomicAdd(&g_acc[1], 0.0);
            double ob = atomicAdd(&g_acc[2], 0.0);
            double cl = atomicAdd(&g_acc[3], 0.0);
            double l2 = atomicAdd(&g_acc[4], 0.0);
            dout[0] = (float)(xy + wh + ob + cl);
            dout[1] = (float)xy;
            dout[2] = (float)wh;
            dout[3] = (float)ob;
            dout[4] = (float)cl;
            dout[5] = (float)l2;
            g_acc[0]=0.0; g_acc[1]=0.0; g_acc[2]=0.0; g_acc[3]=0.0; g_acc[4]=0.0;
            __threadfence();
        }
    }
}

extern "C" void kernel_launch(void* const* d_in, const int* in_sizes, int n_in,
                              void* d_out, int out_size)
{
    const float* xin    = (const float*)d_in[0];
    const float* labels = (const float*)d_in[1];
    const float* cw     = (const float*)d_in[2];
    const float* cb     = (const float*)d_in[3];
    float* dout = (float*)d_out;

    static int smem_set = 0;
    int smem = (int)sizeof(SMem);
    if (!smem_set){
        cudaFuncSetAttribute(k_main, cudaFuncAttributeMaxDynamicSharedMemorySize, smem);
        smem_set = 1;
    }
    dim3 g(NBLK, BB);   /* 37 x 16 = 592 blocks = exactly 4.0/SM, 40 warps/SM */
    k_main<<<g, TPB, smem>>>(xin, labels, cw, cb, dout);
}